// round 12
// baseline (speedup 1.0000x reference)
#include <cuda_runtime.h>
#include <math.h>
#include <stdint.h>

// Problem constants
#define BB  64
#define SS  512
#define HH  768
#define NN  128
#define EE  1024
#define GHD 128
#define FHD 256
#define LL  2
#define BNN (BB*NN)   // 8192
#define STG 6         // segsum pipeline depth
#define APITCH 20     // As row pitch (floats) - conflict-free
#define BPITCH 136    // Bs row pitch (floats) - conflict-free

// ---------------- scratch (device globals; no allocation allowed) ----------------
__device__ float g_gate[BB*SS];
__device__ float g_nf[(size_t)BNN*HH];        // 25 MB
__device__ float g_adjT[(size_t)BB*NN*NN];    // 4 MB, [b][s][d]
__device__ float g_x1a[(size_t)BNN*GHD];
__device__ float g_x1b[(size_t)BNN*GHD];
__device__ float g_h1[(size_t)BNN*GHD];
__device__ float g_x2[(size_t)BNN*GHD];
__device__ float g_pool[BB*GHD];

// ---------------- helpers ----------------
__device__ __forceinline__ void cp16(void* smem, const void* g) {
    unsigned a = (unsigned)__cvta_generic_to_shared(smem);
    asm volatile("cp.async.cg.shared.global [%0], [%1], 16;\n" :: "r"(a), "l"(g));
}
__device__ __forceinline__ unsigned long long dup2(float a) {
    unsigned long long r;
    asm("mov.b64 %0, {%1, %1};" : "=l"(r) : "f"(a));
    return r;
}
__device__ __forceinline__ void ffma2(unsigned long long& d, unsigned long long a,
                                      unsigned long long b) {
    asm("fma.rn.f32x2 %0, %1, %2, %0;" : "+l"(d) : "l"(a), "l"(b));
}
__device__ __forceinline__ void red_sh(uint32_t addr, float v) {
    asm volatile("red.shared.add.f32 [%0], %1;" :: "r"(addr), "f"(v) : "memory");
}
__device__ __forceinline__ void mma_tf32(float* c, const uint32_t* a,
                                         uint32_t b0, uint32_t b1) {
    asm volatile(
        "mma.sync.aligned.m16n8k8.row.col.f32.tf32.tf32.f32 "
        "{%0,%1,%2,%3}, {%4,%5,%6,%7}, {%8,%9}, {%0,%1,%2,%3};"
        : "+f"(c[0]), "+f"(c[1]), "+f"(c[2]), "+f"(c[3])
        : "r"(a[0]), "r"(a[1]), "r"(a[2]), "r"(a[3]), "r"(b0), "r"(b1));
}

// ---------------- K1: gate = sigmoid(lh . wr + br) ----------------
__global__ void k_gate(const float* __restrict__ lh,
                       const float* __restrict__ wr, const float* __restrict__ brp) {
    int warp = (blockIdx.x*blockDim.x + threadIdx.x) >> 5;
    int lane = threadIdx.x & 31;
    if (warp >= BB*SS) return;
    const float4* row4 = (const float4*)(lh + (size_t)warp*HH);
    const float4* w4   = (const float4*)wr;
    float dot = 0.f;
    #pragma unroll
    for (int i = 0; i < 6; i++) {
        float4 a = row4[lane + 32*i];
        float4 w = w4[lane + 32*i];
        dot += a.x*w.x + a.y*w.y + a.z*w.z + a.w*w.w;
    }
    #pragma unroll
    for (int off = 16; off; off >>= 1) dot += __shfl_xor_sync(0xffffffffu, dot, off);
    if (lane == 0)
        g_gate[warp] = 1.f/(1.f + expf(-(dot + brp[0])));
}

// ---------------- K2: segment mean — cp.async streaming + red.shared scatter ------
__global__ void k_segsum(const float* __restrict__ lh, const int* __restrict__ submap) {
    extern __shared__ float sm[];
    float* acc    = sm;                       // NN*128 (64 KB)
    float* stage  = sm + NN*128;              // STG*8*128 (24 KB)
    float* gate_s = stage + STG*1024;         // SS
    float* rc     = gate_s + SS;              // NN
    int*   sub_s  = (int*)(rc + NN);          // SS
    int*   cnt_s  = sub_s + SS;               // NN
    int b = blockIdx.y, c0 = blockIdx.x*128, tid = threadIdx.x;
    uint32_t accA;
    {
        unsigned a = (unsigned)__cvta_generic_to_shared(acc);
        accA = a + tid*4u;
    }

    const float* base = lh + (size_t)b*SS*HH + c0;
    int r  = tid >> 5;          // 0..3
    int c4 = (tid & 31)*4;
    #pragma unroll
    for (int st = 0; st < STG; st++) {
        const float* p = base + (size_t)(st*8)*HH;
        cp16(&stage[st*1024 + r*128 + c4],     p + (size_t)r*HH + c4);
        cp16(&stage[st*1024 + (r+4)*128 + c4], p + (size_t)(r+4)*HH + c4);
        asm volatile("cp.async.commit_group;\n" ::: "memory");
    }

    float4* a4 = (float4*)acc;
    for (int i = tid; i < NN*32; i += 128) a4[i] = make_float4(0.f,0.f,0.f,0.f);
    if (tid < NN) cnt_s[tid] = 0;
    for (int s = tid; s < SS; s += 128) {
        gate_s[s] = g_gate[b*SS + s];
        sub_s[s]  = submap[b*SS + s];
    }
    __syncthreads();
    for (int s = tid; s < SS; s += 128) atomicAdd(&cnt_s[sub_s[s]], 1);

    for (int s0 = 0; s0 < SS; s0 += 8) {
        int st = (s0 >> 3) % STG;
        asm volatile("cp.async.wait_group %0;\n" :: "n"(STG-1) : "memory");
        __syncthreads();
        float v[8];
        #pragma unroll
        for (int j = 0; j < 8; j++) v[j] = stage[st*1024 + j*128 + tid];
        __syncthreads();
        int sn = s0 + STG*8;
        if (sn < SS) {
            const float* p = base + (size_t)sn*HH;
            cp16(&stage[st*1024 + r*128 + c4],     p + (size_t)r*HH + c4);
            cp16(&stage[st*1024 + (r+4)*128 + c4], p + (size_t)(r+4)*HH + c4);
        }
        asm volatile("cp.async.commit_group;\n" ::: "memory");
        #pragma unroll
        for (int j = 0; j < 8; j++) {
            int n = sub_s[s0+j];
            red_sh(accA + (uint32_t)n*512u, v[j]*gate_s[s0+j]);   // fire-and-forget
        }
    }
    __syncthreads();
    if (tid < NN) rc[tid] = 1.f/fmaxf((float)cnt_s[tid], 1.f);
    __syncthreads();
    for (int n = 0; n < NN; n++)
        g_nf[((size_t)(b*NN + n))*HH + c0 + tid] = acc[n*128 + tid]*rc[n];
}

// ---------------- K3: build dense normalized adjacency (transposed) ---------------
__global__ void k_adj(const int* __restrict__ ei) {
    extern __shared__ float sm[];
    float* cnt = sm;          // NN*NN, [s][d]
    float* deg = sm + NN*NN;  // NN
    int b = blockIdx.x, tid = threadIdx.x;   // 256 threads
    float4* c4 = (float4*)cnt;
    for (int i = tid; i < NN*NN/4; i += 256) c4[i] = make_float4(0.f,0.f,0.f,0.f);
    if (tid < NN) deg[tid] = 1.f;   // self loop
    __syncthreads();
    const int* sP = ei + (size_t)b*2*EE;
    const int* dP = sP + EE;
    for (int e = tid; e < EE; e += 256) {
        int s = sP[e], d = dP[e];
        atomicAdd(&deg[d], 1.f);
        atomicAdd(&cnt[s*NN + d], 1.f);
    }
    __syncthreads();
    if (tid < NN) deg[tid] = rsqrtf(deg[tid]);
    __syncthreads();
    float* outp = g_adjT + (size_t)b*NN*NN;
    for (int i = tid; i < NN*NN; i += 256) {
        int s = i >> 7, d = i & 127;
        float v = cnt[i] + (s == d ? 1.f : 0.f);
        outp[i] = v * deg[d] * deg[s];
    }
}

// ---------------- K4/K6: tf32 mma.sync GEMM with K-split --------------------------
// C[BNN x 128] = A[:, k0:k0+KC] @ W[k0:k0+KC, :]; raw fp32 in, HW-truncated to tf32.
// 64x128 tile, 128 threads (4 warps: 2m x 2n), warp = 32 rows x 64 cols.
__global__ void __launch_bounds__(128) k_mma(const float* __restrict__ A,
                                             const float* __restrict__ B,
                                             float* __restrict__ Ca,
                                             float* __restrict__ Cb,
                                             int K, int KC) {
    __shared__ float As[2][64][APITCH];    // 10240 B
    __shared__ float Bs[2][16][BPITCH];    // 17408 B
    int tid = threadIdx.x, lane = tid & 31, wid = tid >> 5;
    int wm = wid & 1, wn = wid >> 1;
    int row0 = blockIdx.x*64;
    int k0 = blockIdx.y * KC;
    float* C = blockIdx.y ? Cb : Ca;
    int r = lane >> 2, c = lane & 3;

    auto loadStage = [&](int st, int kk) {
        #pragma unroll
        for (int q = 0; q < 2; q++) {
            int idx = tid*2 + q;           // 256 chunks: 64 rows x 4 k4
            int row = idx >> 2, k4 = (idx & 3)*4;
            cp16(&As[st][row][k4], A + (size_t)(row0 + row)*K + k0 + kk + k4);
        }
        #pragma unroll
        for (int q = 0; q < 4; q++) {
            int idx = tid*4 + q;           // 512 chunks: 16 rows x 32 c4
            int row = idx >> 5, cc = (idx & 31)*4;
            cp16(&Bs[st][row][cc], B + (size_t)(k0 + kk + row)*GHD + cc);
        }
        asm volatile("cp.async.commit_group;\n" ::: "memory");
    };
    loadStage(0, 0);

    float acc[2][8][4];
    #pragma unroll
    for (int t = 0; t < 2; t++)
        #pragma unroll
        for (int j = 0; j < 8; j++)
            #pragma unroll
            for (int q = 0; q < 4; q++) acc[t][j][q] = 0.f;

    int nk = KC >> 4;
    for (int kb = 0; kb < nk; kb++) {
        int st = kb & 1;
        if (kb + 1 < nk) {
            loadStage(st^1, (kb + 1) << 4);
            asm volatile("cp.async.wait_group 1;\n" ::: "memory");
        } else {
            asm volatile("cp.async.wait_group 0;\n" ::: "memory");
        }
        __syncthreads();
        #pragma unroll
        for (int ks = 0; ks < 16; ks += 8) {
            uint32_t a[2][4];
            #pragma unroll
            for (int t = 0; t < 2; t++) {
                int rr = wm*32 + t*16 + r;
                a[t][0] = __float_as_uint(As[st][rr    ][ks + c]);
                a[t][1] = __float_as_uint(As[st][rr + 8][ks + c]);
                a[t][2] = __float_as_uint(As[st][rr    ][ks + c + 4]);
                a[t][3] = __float_as_uint(As[st][rr + 8][ks + c + 4]);
            }
            #pragma unroll
            for (int j = 0; j < 8; j++) {
                int nc = wn*64 + j*8 + r;
                uint32_t b0 = __float_as_uint(Bs[st][ks + c    ][nc]);
                uint32_t b1 = __float_as_uint(Bs[st][ks + c + 4][nc]);
                mma_tf32(acc[0][j], a[0], b0, b1);
                mma_tf32(acc[1][j], a[1], b0, b1);
            }
        }
        __syncthreads();
    }
    #pragma unroll
    for (int t = 0; t < 2; t++) {
        int rr = row0 + wm*32 + t*16 + r;
        #pragma unroll
        for (int j = 0; j < 8; j++) {
            int cc = wn*64 + j*8 + 2*c;
            *(float2*)&C[(size_t)rr*GHD + cc]       = make_float2(acc[t][j][0], acc[t][j][1]);
            *(float2*)&C[(size_t)(rr + 8)*GHD + cc] = make_float2(acc[t][j][2], acc[t][j][3]);
        }
    }
}

// ---------------- K5/K7: GCN aggregation as dense batched GEMM -------------------
template <bool POOL>
__global__ void k_ah(const float* __restrict__ Xa, const float* __restrict__ Xb,
                     const float* __restrict__ bias, float* __restrict__ outp) {
    extern __shared__ float sm[];
    float* At     = sm;                 // NN*NN  (64 KB), [s][d]
    float* Hs     = sm + NN*NN;         // NN*64  (32 KB), [s][c]
    float* red    = Hs + NN*64;         // 32*64
    float* bias_s = red + 32*64;        // 64
    int bx = blockIdx.x;
    int b = bx >> 1, c0 = (bx & 1)*64;
    int tid = threadIdx.x;              // 256
    int tx = tid & 7;                   // cols c = tx*8 .. +7
    int ty = tid >> 3;                  // rows d = ty*4 .. +3

    const float4* aSrc = (const float4*)(g_adjT + (size_t)b*NN*NN);
    float4* aDst = (float4*)At;
    for (int i = tid; i < NN*NN/4; i += 256) aDst[i] = aSrc[i];
    const float* XaB = Xa + (size_t)b*NN*GHD + c0;
    const float* XbB = Xb ? Xb + (size_t)b*NN*GHD + c0 : (const float*)0;
    for (int i = tid; i < NN*16; i += 256) {
        int s = i >> 4, c = (i & 15)*4;
        float4 v = *(const float4*)&XaB[(size_t)s*GHD + c];
        if (XbB) {
            float4 w = *(const float4*)&XbB[(size_t)s*GHD + c];
            v.x += w.x; v.y += w.y; v.z += w.z; v.w += w.w;
        }
        *(float4*)&Hs[s*64 + c] = v;
    }
    if (tid < 64) bias_s[tid] = bias[c0 + tid];
    __syncthreads();

    unsigned long long acc[4][4];
    #pragma unroll
    for (int i = 0; i < 4; i++)
        #pragma unroll
        for (int j = 0; j < 4; j++) acc[i][j] = 0ull;

    #pragma unroll 4
    for (int s = 0; s < NN; s++) {
        float4 av = *(const float4*)&At[s*NN + ty*4];
        ulonglong2 h0 = *(const ulonglong2*)&Hs[s*64 + tx*8];
        ulonglong2 h1 = *(const ulonglong2*)&Hs[s*64 + tx*8 + 4];
        unsigned long long d0 = dup2(av.x), d1 = dup2(av.y);
        unsigned long long d2 = dup2(av.z), d3 = dup2(av.w);
        ffma2(acc[0][0], d0, h0.x); ffma2(acc[0][1], d0, h0.y);
        ffma2(acc[0][2], d0, h1.x); ffma2(acc[0][3], d0, h1.y);
        ffma2(acc[1][0], d1, h0.x); ffma2(acc[1][1], d1, h0.y);
        ffma2(acc[1][2], d1, h1.x); ffma2(acc[1][3], d1, h1.y);
        ffma2(acc[2][0], d2, h0.x); ffma2(acc[2][1], d2, h0.y);
        ffma2(acc[2][2], d2, h1.x); ffma2(acc[2][3], d2, h1.y);
        ffma2(acc[3][0], d3, h0.x); ffma2(acc[3][1], d3, h0.y);
        ffma2(acc[3][2], d3, h1.x); ffma2(acc[3][3], d3, h1.y);
    }

    float bb[8];
    #pragma unroll
    for (int j = 0; j < 8; j++) bb[j] = bias_s[tx*8 + j];
    float ps[8];
    #pragma unroll
    for (int j = 0; j < 8; j++) ps[j] = 0.f;
    #pragma unroll
    for (int i = 0; i < 4; i++) {
        float v[8];
        #pragma unroll
        for (int p = 0; p < 4; p++) {
            float2 pr = *(float2*)&acc[i][p];
            v[2*p]   = fmaxf(pr.x + bb[2*p],   0.f);
            v[2*p+1] = fmaxf(pr.y + bb[2*p+1], 0.f);
        }
        if (!POOL) {
            int d = ty*4 + i;
            float* orow = outp + (size_t)b*NN*GHD + (size_t)d*GHD + c0 + tx*8;
            *(float4*)orow       = make_float4(v[0], v[1], v[2], v[3]);
            *(float4*)(orow + 4) = make_float4(v[4], v[5], v[6], v[7]);
        } else {
            #pragma unroll
            for (int j = 0; j < 8; j++) ps[j] += v[j];
        }
    }
    if (POOL) {
        *(float4*)&red[ty*64 + tx*8]     = make_float4(ps[0], ps[1], ps[2], ps[3]);
        *(float4*)&red[ty*64 + tx*8 + 4] = make_float4(ps[4], ps[5], ps[6], ps[7]);
        __syncthreads();
        if (tid < 64) {
            float ssum = 0.f;
            #pragma unroll
            for (int g = 0; g < 32; g++) ssum += red[g*64 + tid];
            outp[b*GHD + c0 + tid] = ssum * (1.f/NN);
        }
    }
}

// ---------------- K8: final 2-layer MLP (multi-accumulator ILP) ----------------
__global__ void k_fc(const float* __restrict__ lh, const float* __restrict__ Wf1,
                     const float* __restrict__ bf1, const float* __restrict__ Wf2,
                     const float* __restrict__ bf2, float* __restrict__ out) {
    __shared__ float in_s[HH + GHD]; // 896
    __shared__ float hs[FHD];        // 256
    int b = blockIdx.x, tid = threadIdx.x; // 256 threads
    int wid = tid >> 5, lane = tid & 31;
    for (int i = tid; i < HH; i += 256) in_s[i] = lh[(size_t)b*SS*HH + i];
    if (tid < GHD) in_s[HH + tid] = g_pool[b*GHD + tid];
    __syncthreads();
    float a0 = 0.f, a1 = 0.f, a2 = 0.f, a3 = 0.f;
    #pragma unroll 8
    for (int k = 0; k < HH + GHD; k += 4) {
        a0 += in_s[k+0]*Wf1[(size_t)(k+0)*FHD + tid];
        a1 += in_s[k+1]*Wf1[(size_t)(k+1)*FHD + tid];
        a2 += in_s[k+2]*Wf1[(size_t)(k+2)*FHD + tid];
        a3 += in_s[k+3]*Wf1[(size_t)(k+3)*FHD + tid];
    }
    hs[tid] = fmaxf(bf1[tid] + (a0 + a1) + (a2 + a3), 0.f);
    __syncthreads();
    if (wid < LL) {   // warp wid computes output wid via shuffle reduce
        float o = 0.f;
        #pragma unroll
        for (int q = 0; q < FHD/32; q++)
            o += hs[q*32 + lane]*Wf2[(q*32 + lane)*LL + wid];
        #pragma unroll
        for (int off = 16; off; off >>= 1) o += __shfl_xor_sync(0xffffffffu, o, off);
        if (lane == 0) out[b*LL + wid] = o + bf2[wid];
    }
}

// ---------------- launch ----------------
extern "C" void kernel_launch(void* const* d_in, const int* in_sizes, int n_in,
                              void* d_out, int out_size) {
    const float* lh     = (const float*)d_in[0];
    const int*   submap = (const int*)d_in[1];
    const int*   ei     = (const int*)d_in[2];
    int wbase = (in_sizes[3] == 1) ? 3 : 2;  // num_nodes may be materialized
    const float* wr  = (const float*)d_in[wbase + 1];
    const float* br  = (const float*)d_in[wbase + 2];
    const float* W1  = (const float*)d_in[wbase + 3];
    const float* b1  = (const float*)d_in[wbase + 4];
    const float* W2  = (const float*)d_in[wbase + 5];
    const float* b2  = (const float*)d_in[wbase + 6];
    const float* Wf1 = (const float*)d_in[wbase + 7];
    const float* bf1 = (const float*)d_in[wbase + 8];
    const float* Wf2 = (const float*)d_in[wbase + 9];
    const float* bf2 = (const float*)d_in[wbase + 10];
    float* out = (float*)d_out;

    float *p_nf, *p_x1a, *p_x1b, *p_h1, *p_x2, *p_pool;
    cudaGetSymbolAddress((void**)&p_nf,   g_nf);
    cudaGetSymbolAddress((void**)&p_x1a,  g_x1a);
    cudaGetSymbolAddress((void**)&p_x1b,  g_x1b);
    cudaGetSymbolAddress((void**)&p_h1,   g_h1);
    cudaGetSymbolAddress((void**)&p_x2,   g_x2);
    cudaGetSymbolAddress((void**)&p_pool, g_pool);

    const int smem_seg = (NN*128 + STG*1024 + SS + NN)*sizeof(float)
                       + (SS + NN)*sizeof(int);                                     // ~95 KB
    const int smem_adj = (NN*NN + NN)*sizeof(float);                                // ~66 KB
    const int smem_ah  = (NN*NN + NN*64 + 32*64 + 64)*sizeof(float);                // ~104.5 KB
    cudaFuncSetAttribute(k_segsum,    cudaFuncAttributeMaxDynamicSharedMemorySize, smem_seg);
    cudaFuncSetAttribute(k_adj,       cudaFuncAttributeMaxDynamicSharedMemorySize, smem_adj);
    cudaFuncSetAttribute(k_ah<false>, cudaFuncAttributeMaxDynamicSharedMemorySize, smem_ah);
    cudaFuncSetAttribute(k_ah<true>,  cudaFuncAttributeMaxDynamicSharedMemorySize, smem_ah);

    k_gate<<<(BB*SS*32)/256, 256>>>(lh, wr, br);
    k_segsum<<<dim3(6, BB), 128, smem_seg>>>(lh, submap);
    k_adj<<<BB, 256, smem_adj>>>(ei);
    // GEMM1: K=768 split into two 384-halves (y-dim), disjoint outputs
    k_mma<<<dim3(BNN/64, 2), 128>>>(p_nf, W1, p_x1a, p_x1b, HH, HH/2);
    k_ah<false><<<BB*2, 256, smem_ah>>>(p_x1a, p_x1b, b1, p_h1);
    // GEMM2: K=128, no split
    k_mma<<<dim3(BNN/64, 1), 128>>>(p_h1, W2, p_x2, p_x2, GHD, GHD);
    k_ah<true><<<BB*2, 256, smem_ah>>>(p_x2, (const float*)0, b2, p_pool);
    k_fc<<<BB, 256>>>(lh, Wf1, bf1, Wf2, bf2, out);
}

// round 13
// speedup vs baseline: 1.1952x; 1.1952x over previous
#include <cuda_runtime.h>
#include <math.h>
#include <stdint.h>

// Problem constants
#define BB  64
#define SS  512
#define HH  768
#define NN  128
#define EE  1024
#define GHD 128
#define FHD 256
#define LL  2
#define BNN (BB*NN)   // 8192
#define STG 6         // segsum pipeline depth
#define APITCH 20     // As row pitch (floats) - conflict-free
#define BPITCH 136    // Bs row pitch (floats) - conflict-free

// ---------------- scratch (device globals; no allocation allowed) ----------------
__device__ float g_gate[BB*SS];
__device__ float g_nf[(size_t)BNN*HH];        // 25 MB
__device__ float g_adjT[(size_t)BB*NN*NN];    // 4 MB, [b][s][d]
__device__ float g_x1a[(size_t)BNN*GHD];
__device__ float g_x1b[(size_t)BNN*GHD];
__device__ float g_h1[(size_t)BNN*GHD];
__device__ float g_x2[(size_t)BNN*GHD];
__device__ float g_pool[BB*GHD];

// ---------------- helpers ----------------
__device__ __forceinline__ void cp16(void* smem, const void* g) {
    unsigned a = (unsigned)__cvta_generic_to_shared(smem);
    asm volatile("cp.async.cg.shared.global [%0], [%1], 16;\n" :: "r"(a), "l"(g));
}
__device__ __forceinline__ unsigned long long dup2(float a) {
    unsigned long long r;
    asm("mov.b64 %0, {%1, %1};" : "=l"(r) : "f"(a));
    return r;
}
__device__ __forceinline__ void ffma2(unsigned long long& d, unsigned long long a,
                                      unsigned long long b) {
    asm("fma.rn.f32x2 %0, %1, %2, %0;" : "+l"(d) : "l"(a), "l"(b));
}
__device__ __forceinline__ void mma_tf32(float* c, const uint32_t* a,
                                         uint32_t b0, uint32_t b1) {
    asm volatile(
        "mma.sync.aligned.m16n8k8.row.col.f32.tf32.tf32.f32 "
        "{%0,%1,%2,%3}, {%4,%5,%6,%7}, {%8,%9}, {%0,%1,%2,%3};"
        : "+f"(c[0]), "+f"(c[1]), "+f"(c[2]), "+f"(c[3])
        : "r"(a[0]), "r"(a[1]), "r"(a[2]), "r"(a[3]), "r"(b0), "r"(b1));
}

// ---------------- K1: gate = sigmoid(lh . wr + br) ----------------
__global__ void k_gate(const float* __restrict__ lh,
                       const float* __restrict__ wr, const float* __restrict__ brp) {
    int warp = (blockIdx.x*blockDim.x + threadIdx.x) >> 5;
    int lane = threadIdx.x & 31;
    if (warp >= BB*SS) return;
    const float4* row4 = (const float4*)(lh + (size_t)warp*HH);
    const float4* w4   = (const float4*)wr;
    float dot = 0.f;
    #pragma unroll
    for (int i = 0; i < 6; i++) {
        float4 a = row4[lane + 32*i];
        float4 w = w4[lane + 32*i];
        dot += a.x*w.x + a.y*w.y + a.z*w.z + a.w*w.w;
    }
    #pragma unroll
    for (int off = 16; off; off >>= 1) dot += __shfl_xor_sync(0xffffffffu, dot, off);
    if (lane == 0)
        g_gate[warp] = 1.f/(1.f + expf(-(dot + brp[0])));
}

// ---------------- K2: segment mean — cp.async streaming, thread-private columns ---
__global__ void k_segsum(const float* __restrict__ lh, const int* __restrict__ submap) {
    extern __shared__ float sm[];
    float* acc    = sm;                       // NN*128 (64 KB)
    float* stage  = sm + NN*128;              // STG*8*128 (24 KB)
    float* gate_s = stage + STG*1024;         // SS
    float* rc     = gate_s + SS;              // NN
    int*   sub_s  = (int*)(rc + NN);          // SS
    int*   cnt_s  = sub_s + SS;               // NN
    int b = blockIdx.y, c0 = blockIdx.x*128, tid = threadIdx.x;

    const float* base = lh + (size_t)b*SS*HH + c0;
    int r  = tid >> 5;          // 0..3
    int c4 = (tid & 31)*4;
    #pragma unroll
    for (int st = 0; st < STG; st++) {
        const float* p = base + (size_t)(st*8)*HH;
        cp16(&stage[st*1024 + r*128 + c4],     p + (size_t)r*HH + c4);
        cp16(&stage[st*1024 + (r+4)*128 + c4], p + (size_t)(r+4)*HH + c4);
        asm volatile("cp.async.commit_group;\n" ::: "memory");
    }

    float4* a4 = (float4*)acc;
    for (int i = tid; i < NN*32; i += 128) a4[i] = make_float4(0.f,0.f,0.f,0.f);
    if (tid < NN) cnt_s[tid] = 0;
    for (int s = tid; s < SS; s += 128) {
        gate_s[s] = g_gate[b*SS + s];
        sub_s[s]  = submap[b*SS + s];
    }
    __syncthreads();
    for (int s = tid; s < SS; s += 128) atomicAdd(&cnt_s[sub_s[s]], 1);

    for (int s0 = 0; s0 < SS; s0 += 8) {
        int st = (s0 >> 3) % STG;
        asm volatile("cp.async.wait_group %0;\n" :: "n"(STG-1) : "memory");
        __syncthreads();
        float v[8];
        #pragma unroll
        for (int j = 0; j < 8; j++) v[j] = stage[st*1024 + j*128 + tid];
        __syncthreads();                     // all reads done before refill
        int sn = s0 + STG*8;
        if (sn < SS) {
            const float* p = base + (size_t)sn*HH;
            cp16(&stage[st*1024 + r*128 + c4],     p + (size_t)r*HH + c4);
            cp16(&stage[st*1024 + (r+4)*128 + c4], p + (size_t)(r+4)*HH + c4);
        }
        asm volatile("cp.async.commit_group;\n" ::: "memory");
        #pragma unroll
        for (int j = 0; j < 8; j++) {
            int n = sub_s[s0+j];
            acc[n*128 + tid] += v[j]*gate_s[s0+j];   // private column: no atomic
        }
    }
    __syncthreads();
    if (tid < NN) rc[tid] = 1.f/fmaxf((float)cnt_s[tid], 1.f);
    __syncthreads();
    for (int n = 0; n < NN; n++)
        g_nf[((size_t)(b*NN + n))*HH + c0 + tid] = acc[n*128 + tid]*rc[n];
}

// ---------------- K3: build dense normalized adjacency (transposed) ---------------
__global__ void k_adj(const int* __restrict__ ei) {
    extern __shared__ float sm[];
    float* cnt = sm;          // NN*NN, [s][d]
    float* deg = sm + NN*NN;  // NN
    int b = blockIdx.x, tid = threadIdx.x;   // 256 threads
    float4* c4 = (float4*)cnt;
    for (int i = tid; i < NN*NN/4; i += 256) c4[i] = make_float4(0.f,0.f,0.f,0.f);
    if (tid < NN) deg[tid] = 1.f;   // self loop
    __syncthreads();
    const int* sP = ei + (size_t)b*2*EE;
    const int* dP = sP + EE;
    for (int e = tid; e < EE; e += 256) {
        int s = sP[e], d = dP[e];
        atomicAdd(&deg[d], 1.f);
        atomicAdd(&cnt[s*NN + d], 1.f);
    }
    __syncthreads();
    if (tid < NN) deg[tid] = rsqrtf(deg[tid]);
    __syncthreads();
    float* outp = g_adjT + (size_t)b*NN*NN;
    for (int i = tid; i < NN*NN; i += 256) {
        int s = i >> 7, d = i & 127;
        float v = cnt[i] + (s == d ? 1.f : 0.f);
        outp[i] = v * deg[d] * deg[s];
    }
}

// ---------------- K4/K6: tf32 mma.sync GEMM with K-split --------------------------
// C[BNN x 128] = A[:, k0:k0+KC] @ W[k0:k0+KC, :]; raw fp32 in, HW-truncated to tf32.
// 64x128 tile, 128 threads (4 warps: 2m x 2n), warp = 32 rows x 64 cols.
__global__ void __launch_bounds__(128) k_mma(const float* __restrict__ A,
                                             const float* __restrict__ B,
                                             float* __restrict__ Ca,
                                             float* __restrict__ Cb,
                                             int K, int KC) {
    __shared__ float As[2][64][APITCH];    // 10240 B
    __shared__ float Bs[2][16][BPITCH];    // 17408 B
    int tid = threadIdx.x, lane = tid & 31, wid = tid >> 5;
    int wm = wid & 1, wn = wid >> 1;
    int row0 = blockIdx.x*64;
    int k0 = blockIdx.y * KC;
    float* C = blockIdx.y ? Cb : Ca;
    int r = lane >> 2, c = lane & 3;

    auto loadStage = [&](int st, int kk) {
        #pragma unroll
        for (int q = 0; q < 2; q++) {
            int idx = tid*2 + q;           // 256 chunks: 64 rows x 4 k4
            int row = idx >> 2, k4 = (idx & 3)*4;
            cp16(&As[st][row][k4], A + (size_t)(row0 + row)*K + k0 + kk + k4);
        }
        #pragma unroll
        for (int q = 0; q < 4; q++) {
            int idx = tid*4 + q;           // 512 chunks: 16 rows x 32 c4
            int row = idx >> 5, cc = (idx & 31)*4;
            cp16(&Bs[st][row][cc], B + (size_t)(k0 + kk + row)*GHD + cc);
        }
        asm volatile("cp.async.commit_group;\n" ::: "memory");
    };
    loadStage(0, 0);

    float acc[2][8][4];
    #pragma unroll
    for (int t = 0; t < 2; t++)
        #pragma unroll
        for (int j = 0; j < 8; j++)
            #pragma unroll
            for (int q = 0; q < 4; q++) acc[t][j][q] = 0.f;

    int nk = KC >> 4;
    for (int kb = 0; kb < nk; kb++) {
        int st = kb & 1;
        if (kb + 1 < nk) {
            loadStage(st^1, (kb + 1) << 4);
            asm volatile("cp.async.wait_group 1;\n" ::: "memory");
        } else {
            asm volatile("cp.async.wait_group 0;\n" ::: "memory");
        }
        __syncthreads();
        #pragma unroll
        for (int ks = 0; ks < 16; ks += 8) {
            uint32_t a[2][4];
            #pragma unroll
            for (int t = 0; t < 2; t++) {
                int rr = wm*32 + t*16 + r;
                a[t][0] = __float_as_uint(As[st][rr    ][ks + c]);
                a[t][1] = __float_as_uint(As[st][rr + 8][ks + c]);
                a[t][2] = __float_as_uint(As[st][rr    ][ks + c + 4]);
                a[t][3] = __float_as_uint(As[st][rr + 8][ks + c + 4]);
            }
            #pragma unroll
            for (int j = 0; j < 8; j++) {
                int nc = wn*64 + j*8 + r;
                uint32_t b0 = __float_as_uint(Bs[st][ks + c    ][nc]);
                uint32_t b1 = __float_as_uint(Bs[st][ks + c + 4][nc]);
                mma_tf32(acc[0][j], a[0], b0, b1);
                mma_tf32(acc[1][j], a[1], b0, b1);
            }
        }
        __syncthreads();
    }
    #pragma unroll
    for (int t = 0; t < 2; t++) {
        int rr = row0 + wm*32 + t*16 + r;
        #pragma unroll
        for (int j = 0; j < 8; j++) {
            int cc = wn*64 + j*8 + 2*c;
            *(float2*)&C[(size_t)rr*GHD + cc]       = make_float2(acc[t][j][0], acc[t][j][1]);
            *(float2*)&C[(size_t)(rr + 8)*GHD + cc] = make_float2(acc[t][j][2], acc[t][j][3]);
        }
    }
}

// ---------------- K5/K7: GCN aggregation as dense batched GEMM -------------------
template <bool POOL>
__global__ void k_ah(const float* __restrict__ Xa, const float* __restrict__ Xb,
                     const float* __restrict__ bias, float* __restrict__ outp) {
    extern __shared__ float sm[];
    float* At     = sm;                 // NN*NN  (64 KB), [s][d]
    float* Hs     = sm + NN*NN;         // NN*64  (32 KB), [s][c]
    float* red    = Hs + NN*64;         // 32*64
    float* bias_s = red + 32*64;        // 64
    int bx = blockIdx.x;
    int b = bx >> 1, c0 = (bx & 1)*64;
    int tid = threadIdx.x;              // 256
    int tx = tid & 7;                   // cols c = tx*8 .. +7
    int ty = tid >> 3;                  // rows d = ty*4 .. +3

    const float4* aSrc = (const float4*)(g_adjT + (size_t)b*NN*NN);
    float4* aDst = (float4*)At;
    for (int i = tid; i < NN*NN/4; i += 256) aDst[i] = aSrc[i];
    const float* XaB = Xa + (size_t)b*NN*GHD + c0;
    const float* XbB = Xb ? Xb + (size_t)b*NN*GHD + c0 : (const float*)0;
    for (int i = tid; i < NN*16; i += 256) {
        int s = i >> 4, c = (i & 15)*4;
        float4 v = *(const float4*)&XaB[(size_t)s*GHD + c];
        if (XbB) {
            float4 w = *(const float4*)&XbB[(size_t)s*GHD + c];
            v.x += w.x; v.y += w.y; v.z += w.z; v.w += w.w;
        }
        *(float4*)&Hs[s*64 + c] = v;
    }
    if (tid < 64) bias_s[tid] = bias[c0 + tid];
    __syncthreads();

    unsigned long long acc[4][4];
    #pragma unroll
    for (int i = 0; i < 4; i++)
        #pragma unroll
        for (int j = 0; j < 4; j++) acc[i][j] = 0ull;

    #pragma unroll 4
    for (int s = 0; s < NN; s++) {
        float4 av = *(const float4*)&At[s*NN + ty*4];
        ulonglong2 h0 = *(const ulonglong2*)&Hs[s*64 + tx*8];
        ulonglong2 h1 = *(const ulonglong2*)&Hs[s*64 + tx*8 + 4];
        unsigned long long d0 = dup2(av.x), d1 = dup2(av.y);
        unsigned long long d2 = dup2(av.z), d3 = dup2(av.w);
        ffma2(acc[0][0], d0, h0.x); ffma2(acc[0][1], d0, h0.y);
        ffma2(acc[0][2], d0, h1.x); ffma2(acc[0][3], d0, h1.y);
        ffma2(acc[1][0], d1, h0.x); ffma2(acc[1][1], d1, h0.y);
        ffma2(acc[1][2], d1, h1.x); ffma2(acc[1][3], d1, h1.y);
        ffma2(acc[2][0], d2, h0.x); ffma2(acc[2][1], d2, h0.y);
        ffma2(acc[2][2], d2, h1.x); ffma2(acc[2][3], d2, h1.y);
        ffma2(acc[3][0], d3, h0.x); ffma2(acc[3][1], d3, h0.y);
        ffma2(acc[3][2], d3, h1.x); ffma2(acc[3][3], d3, h1.y);
    }

    float bb[8];
    #pragma unroll
    for (int j = 0; j < 8; j++) bb[j] = bias_s[tx*8 + j];
    float ps[8];
    #pragma unroll
    for (int j = 0; j < 8; j++) ps[j] = 0.f;
    #pragma unroll
    for (int i = 0; i < 4; i++) {
        float v[8];
        #pragma unroll
        for (int p = 0; p < 4; p++) {
            float2 pr = *(float2*)&acc[i][p];
            v[2*p]   = fmaxf(pr.x + bb[2*p],   0.f);
            v[2*p+1] = fmaxf(pr.y + bb[2*p+1], 0.f);
        }
        if (!POOL) {
            int d = ty*4 + i;
            float* orow = outp + (size_t)b*NN*GHD + (size_t)d*GHD + c0 + tx*8;
            *(float4*)orow       = make_float4(v[0], v[1], v[2], v[3]);
            *(float4*)(orow + 4) = make_float4(v[4], v[5], v[6], v[7]);
        } else {
            #pragma unroll
            for (int j = 0; j < 8; j++) ps[j] += v[j];
        }
    }
    if (POOL) {
        *(float4*)&red[ty*64 + tx*8]     = make_float4(ps[0], ps[1], ps[2], ps[3]);
        *(float4*)&red[ty*64 + tx*8 + 4] = make_float4(ps[4], ps[5], ps[6], ps[7]);
        __syncthreads();
        if (tid < 64) {
            float ssum = 0.f;
            #pragma unroll
            for (int g = 0; g < 32; g++) ssum += red[g*64 + tid];
            outp[b*GHD + c0 + tid] = ssum * (1.f/NN);
        }
    }
}

// ---------------- K8: final 2-layer MLP (multi-accumulator ILP) ----------------
__global__ void k_fc(const float* __restrict__ lh, const float* __restrict__ Wf1,
                     const float* __restrict__ bf1, const float* __restrict__ Wf2,
                     const float* __restrict__ bf2, float* __restrict__ out) {
    __shared__ float in_s[HH + GHD]; // 896
    __shared__ float hs[FHD];        // 256
    int b = blockIdx.x, tid = threadIdx.x; // 256 threads
    int wid = tid >> 5, lane = tid & 31;
    for (int i = tid; i < HH; i += 256) in_s[i] = lh[(size_t)b*SS*HH + i];
    if (tid < GHD) in_s[HH + tid] = g_pool[b*GHD + tid];
    __syncthreads();
    float a0 = 0.f, a1 = 0.f, a2 = 0.f, a3 = 0.f;
    #pragma unroll 8
    for (int k = 0; k < HH + GHD; k += 4) {
        a0 += in_s[k+0]*Wf1[(size_t)(k+0)*FHD + tid];
        a1 += in_s[k+1]*Wf1[(size_t)(k+1)*FHD + tid];
        a2 += in_s[k+2]*Wf1[(size_t)(k+2)*FHD + tid];
        a3 += in_s[k+3]*Wf1[(size_t)(k+3)*FHD + tid];
    }
    hs[tid] = fmaxf(bf1[tid] + (a0 + a1) + (a2 + a3), 0.f);
    __syncthreads();
    if (wid < LL) {   // warp wid computes output wid via shuffle reduce
        float o = 0.f;
        #pragma unroll
        for (int q = 0; q < FHD/32; q++)
            o += hs[q*32 + lane]*Wf2[(q*32 + lane)*LL + wid];
        #pragma unroll
        for (int off = 16; off; off >>= 1) o += __shfl_xor_sync(0xffffffffu, o, off);
        if (lane == 0) out[b*LL + wid] = o + bf2[wid];
    }
}

// ---------------- launch ----------------
extern "C" void kernel_launch(void* const* d_in, const int* in_sizes, int n_in,
                              void* d_out, int out_size) {
    const float* lh     = (const float*)d_in[0];
    const int*   submap = (const int*)d_in[1];
    const int*   ei     = (const int*)d_in[2];
    int wbase = (in_sizes[3] == 1) ? 3 : 2;  // num_nodes may be materialized
    const float* wr  = (const float*)d_in[wbase + 1];
    const float* br  = (const float*)d_in[wbase + 2];
    const float* W1  = (const float*)d_in[wbase + 3];
    const float* b1  = (const float*)d_in[wbase + 4];
    const float* W2  = (const float*)d_in[wbase + 5];
    const float* b2  = (const float*)d_in[wbase + 6];
    const float* Wf1 = (const float*)d_in[wbase + 7];
    const float* bf1 = (const float*)d_in[wbase + 8];
    const float* Wf2 = (const float*)d_in[wbase + 9];
    const float* bf2 = (const float*)d_in[wbase + 10];
    float* out = (float*)d_out;

    float *p_nf, *p_x1a, *p_x1b, *p_h1, *p_x2, *p_pool;
    cudaGetSymbolAddress((void**)&p_nf,   g_nf);
    cudaGetSymbolAddress((void**)&p_x1a,  g_x1a);
    cudaGetSymbolAddress((void**)&p_x1b,  g_x1b);
    cudaGetSymbolAddress((void**)&p_h1,   g_h1);
    cudaGetSymbolAddress((void**)&p_x2,   g_x2);
    cudaGetSymbolAddress((void**)&p_pool, g_pool);

    const int smem_seg = (NN*128 + STG*1024 + SS + NN)*sizeof(float)
                       + (SS + NN)*sizeof(int);                                     // ~95 KB
    const int smem_adj = (NN*NN + NN)*sizeof(float);                                // ~66 KB
    const int smem_ah  = (NN*NN + NN*64 + 32*64 + 64)*sizeof(float);                // ~104.5 KB
    cudaFuncSetAttribute(k_segsum,    cudaFuncAttributeMaxDynamicSharedMemorySize, smem_seg);
    cudaFuncSetAttribute(k_adj,       cudaFuncAttributeMaxDynamicSharedMemorySize, smem_adj);
    cudaFuncSetAttribute(k_ah<false>, cudaFuncAttributeMaxDynamicSharedMemorySize, smem_ah);
    cudaFuncSetAttribute(k_ah<true>,  cudaFuncAttributeMaxDynamicSharedMemorySize, smem_ah);

    k_gate<<<(BB*SS*32)/256, 256>>>(lh, wr, br);
    k_segsum<<<dim3(6, BB), 128, smem_seg>>>(lh, submap);
    k_adj<<<BB, 256, smem_adj>>>(ei);
    // GEMM1: K=768 split into two 384-halves (y-dim), disjoint outputs
    k_mma<<<dim3(BNN/64, 2), 128>>>(p_nf, W1, p_x1a, p_x1b, HH, HH/2);
    k_ah<false><<<BB*2, 256, smem_ah>>>(p_x1a, p_x1b, b1, p_h1);
    // GEMM2: K=128, no split
    k_mma<<<dim3(BNN/64, 1), 128>>>(p_h1, W2, p_x2, p_x2, GHD, GHD);
    k_ah<true><<<BB*2, 256, smem_ah>>>(p_x2, (const float*)0, b2, p_pool);
    k_fc<<<BB, 256>>>(lh, Wf1, bf1, Wf2, bf2, out);
}

// round 14
// speedup vs baseline: 1.2572x; 1.0519x over previous
#include <cuda_runtime.h>
#include <math.h>
#include <stdint.h>

// Problem constants
#define BB  64
#define SS  512
#define HH  768
#define NN  128
#define EE  1024
#define GHD 128
#define FHD 256
#define LL  2
#define BNN (BB*NN)   // 8192
#define SST 8         // segsum ring slots
#define SIF 6         // segsum in-flight groups
#define APITCH 20     // As row pitch (floats) - conflict-free
#define BPITCH 136    // Bs row pitch (floats) - conflict-free

// ---------------- scratch (device globals; no allocation allowed) ----------------
__device__ float g_gate[BB*SS];
__device__ float g_nf[(size_t)BNN*HH];        // 25 MB
__device__ float g_adjT[(size_t)BB*NN*NN];    // 4 MB, [b][s][d]
__device__ float g_x1a[(size_t)BNN*GHD];
__device__ float g_x1b[(size_t)BNN*GHD];
__device__ float g_h1[(size_t)BNN*GHD];
__device__ float g_x2[(size_t)BNN*GHD];
__device__ float g_pool[BB*GHD];

// ---------------- helpers ----------------
__device__ __forceinline__ void cp16(void* smem, const void* g) {
    unsigned a = (unsigned)__cvta_generic_to_shared(smem);
    asm volatile("cp.async.cg.shared.global [%0], [%1], 16;\n" :: "r"(a), "l"(g));
}
__device__ __forceinline__ unsigned long long dup2(float a) {
    unsigned long long r;
    asm("mov.b64 %0, {%1, %1};" : "=l"(r) : "f"(a));
    return r;
}
__device__ __forceinline__ void ffma2(unsigned long long& d, unsigned long long a,
                                      unsigned long long b) {
    asm("fma.rn.f32x2 %0, %1, %2, %0;" : "+l"(d) : "l"(a), "l"(b));
}
__device__ __forceinline__ void mma_tf32(float* c, const uint32_t* a,
                                         uint32_t b0, uint32_t b1) {
    asm volatile(
        "mma.sync.aligned.m16n8k8.row.col.f32.tf32.tf32.f32 "
        "{%0,%1,%2,%3}, {%4,%5,%6,%7}, {%8,%9}, {%0,%1,%2,%3};"
        : "+f"(c[0]), "+f"(c[1]), "+f"(c[2]), "+f"(c[3])
        : "r"(a[0]), "r"(a[1]), "r"(a[2]), "r"(a[3]), "r"(b0), "r"(b1));
}

// ---------------- K1: gate = sigmoid(lh . wr + br) ----------------
__global__ void k_gate(const float* __restrict__ lh,
                       const float* __restrict__ wr, const float* __restrict__ brp) {
    int warp = (blockIdx.x*blockDim.x + threadIdx.x) >> 5;
    int lane = threadIdx.x & 31;
    if (warp >= BB*SS) return;
    const float4* row4 = (const float4*)(lh + (size_t)warp*HH);
    const float4* w4   = (const float4*)wr;
    float dot = 0.f;
    #pragma unroll
    for (int i = 0; i < 6; i++) {
        float4 a = row4[lane + 32*i];
        float4 w = w4[lane + 32*i];
        dot += a.x*w.x + a.y*w.y + a.z*w.z + a.w*w.w;
    }
    #pragma unroll
    for (int off = 16; off; off >>= 1) dot += __shfl_xor_sync(0xffffffffu, dot, off);
    if (lane == 0)
        g_gate[warp] = 1.f/(1.f + expf(-(dot + brp[0])));
}

// ---------------- K2: segment mean — 8-slot cp.async ring, one sync per group -----
__global__ void k_segsum(const float* __restrict__ lh, const int* __restrict__ submap) {
    extern __shared__ float sm[];
    float* acc    = sm;                       // NN*128 (64 KB)
    float* stage  = sm + NN*128;              // SST*8*128 (32 KB)
    float* gate_s = stage + SST*1024;         // SS
    float* rc     = gate_s + SS;              // NN
    int*   sub_s  = (int*)(rc + NN);          // SS
    int*   cnt_s  = sub_s + SS;               // NN
    int b = blockIdx.y, c0 = blockIdx.x*128, tid = threadIdx.x;

    const float* base = lh + (size_t)b*SS*HH + c0;
    int r  = tid >> 5;          // 0..3
    int c4 = (tid & 31)*4;
    #pragma unroll
    for (int g = 0; g < SIF; g++) {
        const float* p = base + (size_t)(g*8)*HH;
        cp16(&stage[(g & (SST-1))*1024 + r*128 + c4],     p + (size_t)r*HH + c4);
        cp16(&stage[(g & (SST-1))*1024 + (r+4)*128 + c4], p + (size_t)(r+4)*HH + c4);
        asm volatile("cp.async.commit_group;\n" ::: "memory");
    }

    float4* a4 = (float4*)acc;
    for (int i = tid; i < NN*32; i += 128) a4[i] = make_float4(0.f,0.f,0.f,0.f);
    if (tid < NN) cnt_s[tid] = 0;
    for (int s = tid; s < SS; s += 128) {
        gate_s[s] = g_gate[b*SS + s];
        sub_s[s]  = submap[b*SS + s];
    }
    __syncthreads();
    for (int s = tid; s < SS; s += 128) atomicAdd(&cnt_s[sub_s[s]], 1);

    for (int g = 0; g < SS/8; g++) {
        int st = g & (SST-1);
        asm volatile("cp.async.wait_group %0;\n" :: "n"(SIF-1) : "memory");
        __syncthreads();                        // single barrier per group
        float v[8];
        #pragma unroll
        for (int j = 0; j < 8; j++) v[j] = stage[st*1024 + j*128 + tid];
        int gn = g + SIF;                       // write slot (g+6)&7 != read slot
        if (gn < SS/8) {
            int wn = gn & (SST-1);
            const float* p = base + (size_t)(gn*8)*HH;
            cp16(&stage[wn*1024 + r*128 + c4],     p + (size_t)r*HH + c4);
            cp16(&stage[wn*1024 + (r+4)*128 + c4], p + (size_t)(r+4)*HH + c4);
        }
        asm volatile("cp.async.commit_group;\n" ::: "memory");
        int s0 = g*8;
        #pragma unroll
        for (int j = 0; j < 8; j++) {
            int n = sub_s[s0+j];
            acc[n*128 + tid] += v[j]*gate_s[s0+j];   // private column: no atomic
        }
    }
    __syncthreads();
    if (tid < NN) rc[tid] = 1.f/fmaxf((float)cnt_s[tid], 1.f);
    __syncthreads();
    for (int n = 0; n < NN; n++)
        g_nf[((size_t)(b*NN + n))*HH + c0 + tid] = acc[n*128 + tid]*rc[n];
}

// ---------------- K3: build dense normalized adjacency (transposed) ---------------
__global__ void k_adj(const int* __restrict__ ei) {
    extern __shared__ float sm[];
    float* cnt = sm;          // NN*NN, [s][d]
    float* deg = sm + NN*NN;  // NN
    int b = blockIdx.x, tid = threadIdx.x;   // 256 threads
    float4* c4 = (float4*)cnt;
    for (int i = tid; i < NN*NN/4; i += 256) c4[i] = make_float4(0.f,0.f,0.f,0.f);
    if (tid < NN) deg[tid] = 1.f;   // self loop
    __syncthreads();
    const int* sP = ei + (size_t)b*2*EE;
    const int* dP = sP + EE;
    for (int e = tid; e < EE; e += 256) {
        int s = sP[e], d = dP[e];
        atomicAdd(&deg[d], 1.f);
        atomicAdd(&cnt[s*NN + d], 1.f);
    }
    __syncthreads();
    if (tid < NN) deg[tid] = rsqrtf(deg[tid]);
    __syncthreads();
    float* outp = g_adjT + (size_t)b*NN*NN;
    for (int i = tid; i < NN*NN; i += 256) {
        int s = i >> 7, d = i & 127;
        float v = cnt[i] + (s == d ? 1.f : 0.f);
        outp[i] = v * deg[d] * deg[s];
    }
}

// ---------------- K4/K6: tf32 mma.sync GEMM, 8 warps, K-split ---------------------
// C[BNN x 128] = A[:, k0:k0+KC] @ W[k0:k0+KC, :]; raw fp32, HW tf32 truncation.
// 64x128 tile, 256 threads (8 warps: 4m x 2n), warp = 16 rows x 64 cols.
__global__ void __launch_bounds__(256) k_mma(const float* __restrict__ A,
                                             const float* __restrict__ B,
                                             float* __restrict__ Ca,
                                             float* __restrict__ Cb,
                                             int K, int KC) {
    __shared__ float As[2][64][APITCH];    // 10240 B
    __shared__ float Bs[2][16][BPITCH];    // 17408 B
    int tid = threadIdx.x, lane = tid & 31, wid = tid >> 5;
    int wm = wid & 3, wn = wid >> 2;       // 4 m-slices x 2 n-halves
    int row0 = blockIdx.x*64;
    int k0 = blockIdx.y * KC;
    float* C = blockIdx.y ? Cb : Ca;
    int r = lane >> 2, c = lane & 3;

    auto loadStage = [&](int st, int kk) {
        {   // As: 256 chunks, one per thread (64 rows x 4 k4)
            int row = tid >> 2, k4 = (tid & 3)*4;
            cp16(&As[st][row][k4], A + (size_t)(row0 + row)*K + k0 + kk + k4);
        }
        #pragma unroll
        for (int q = 0; q < 2; q++) {      // Bs: 512 chunks (16 rows x 32 c4)
            int idx = tid*2 + q;
            int row = idx >> 5, cc = (idx & 31)*4;
            cp16(&Bs[st][row][cc], B + (size_t)(k0 + kk + row)*GHD + cc);
        }
        asm volatile("cp.async.commit_group;\n" ::: "memory");
    };
    loadStage(0, 0);

    float acc[8][4];
    #pragma unroll
    for (int j = 0; j < 8; j++)
        #pragma unroll
        for (int q = 0; q < 4; q++) acc[j][q] = 0.f;

    int nk = KC >> 4;
    for (int kb = 0; kb < nk; kb++) {
        int st = kb & 1;
        if (kb + 1 < nk) {
            loadStage(st^1, (kb + 1) << 4);
            asm volatile("cp.async.wait_group 1;\n" ::: "memory");
        } else {
            asm volatile("cp.async.wait_group 0;\n" ::: "memory");
        }
        __syncthreads();
        #pragma unroll
        for (int ks = 0; ks < 16; ks += 8) {
            uint32_t a[4];
            int rr = wm*16 + r;
            a[0] = __float_as_uint(As[st][rr    ][ks + c]);
            a[1] = __float_as_uint(As[st][rr + 8][ks + c]);
            a[2] = __float_as_uint(As[st][rr    ][ks + c + 4]);
            a[3] = __float_as_uint(As[st][rr + 8][ks + c + 4]);
            #pragma unroll
            for (int j = 0; j < 8; j++) {
                int nc = wn*64 + j*8 + r;
                uint32_t b0 = __float_as_uint(Bs[st][ks + c    ][nc]);
                uint32_t b1 = __float_as_uint(Bs[st][ks + c + 4][nc]);
                mma_tf32(acc[j], a, b0, b1);
            }
        }
        __syncthreads();
    }
    {
        int rr = row0 + wm*16 + r;
        #pragma unroll
        for (int j = 0; j < 8; j++) {
            int cc = wn*64 + j*8 + 2*c;
            *(float2*)&C[(size_t)rr*GHD + cc]       = make_float2(acc[j][0], acc[j][1]);
            *(float2*)&C[(size_t)(rr + 8)*GHD + cc] = make_float2(acc[j][2], acc[j][3]);
        }
    }
}

// ---------------- K5/K7: GCN aggregation as dense batched GEMM -------------------
template <bool POOL>
__global__ void k_ah(const float* __restrict__ Xa, const float* __restrict__ Xb,
                     const float* __restrict__ bias, float* __restrict__ outp) {
    extern __shared__ float sm[];
    float* At     = sm;                 // NN*NN  (64 KB), [s][d]
    float* Hs     = sm + NN*NN;         // NN*64  (32 KB), [s][c]
    float* red    = Hs + NN*64;         // 32*64
    float* bias_s = red + 32*64;        // 64
    int bx = blockIdx.x;
    int b = bx >> 1, c0 = (bx & 1)*64;
    int tid = threadIdx.x;              // 256
    int tx = tid & 7;                   // cols c = tx*8 .. +7
    int ty = tid >> 3;                  // rows d = ty*4 .. +3

    const float4* aSrc = (const float4*)(g_adjT + (size_t)b*NN*NN);
    float4* aDst = (float4*)At;
    for (int i = tid; i < NN*NN/4; i += 256) aDst[i] = aSrc[i];
    const float* XaB = Xa + (size_t)b*NN*GHD + c0;
    const float* XbB = Xb ? Xb + (size_t)b*NN*GHD + c0 : (const float*)0;
    for (int i = tid; i < NN*16; i += 256) {
        int s = i >> 4, c = (i & 15)*4;
        float4 v = *(const float4*)&XaB[(size_t)s*GHD + c];
        if (XbB) {
            float4 w = *(const float4*)&XbB[(size_t)s*GHD + c];
            v.x += w.x; v.y += w.y; v.z += w.z; v.w += w.w;
        }
        *(float4*)&Hs[s*64 + c] = v;
    }
    if (tid < 64) bias_s[tid] = bias[c0 + tid];
    __syncthreads();

    unsigned long long acc[4][4];
    #pragma unroll
    for (int i = 0; i < 4; i++)
        #pragma unroll
        for (int j = 0; j < 4; j++) acc[i][j] = 0ull;

    #pragma unroll 4
    for (int s = 0; s < NN; s++) {
        float4 av = *(const float4*)&At[s*NN + ty*4];
        ulonglong2 h0 = *(const ulonglong2*)&Hs[s*64 + tx*8];
        ulonglong2 h1 = *(const ulonglong2*)&Hs[s*64 + tx*8 + 4];
        unsigned long long d0 = dup2(av.x), d1 = dup2(av.y);
        unsigned long long d2 = dup2(av.z), d3 = dup2(av.w);
        ffma2(acc[0][0], d0, h0.x); ffma2(acc[0][1], d0, h0.y);
        ffma2(acc[0][2], d0, h1.x); ffma2(acc[0][3], d0, h1.y);
        ffma2(acc[1][0], d1, h0.x); ffma2(acc[1][1], d1, h0.y);
        ffma2(acc[1][2], d1, h1.x); ffma2(acc[1][3], d1, h1.y);
        ffma2(acc[2][0], d2, h0.x); ffma2(acc[2][1], d2, h0.y);
        ffma2(acc[2][2], d2, h1.x); ffma2(acc[2][3], d2, h1.y);
        ffma2(acc[3][0], d3, h0.x); ffma2(acc[3][1], d3, h0.y);
        ffma2(acc[3][2], d3, h1.x); ffma2(acc[3][3], d3, h1.y);
    }

    float bb[8];
    #pragma unroll
    for (int j = 0; j < 8; j++) bb[j] = bias_s[tx*8 + j];
    float ps[8];
    #pragma unroll
    for (int j = 0; j < 8; j++) ps[j] = 0.f;
    #pragma unroll
    for (int i = 0; i < 4; i++) {
        float v[8];
        #pragma unroll
        for (int p = 0; p < 4; p++) {
            float2 pr = *(float2*)&acc[i][p];
            v[2*p]   = fmaxf(pr.x + bb[2*p],   0.f);
            v[2*p+1] = fmaxf(pr.y + bb[2*p+1], 0.f);
        }
        if (!POOL) {
            int d = ty*4 + i;
            float* orow = outp + (size_t)b*NN*GHD + (size_t)d*GHD + c0 + tx*8;
            *(float4*)orow       = make_float4(v[0], v[1], v[2], v[3]);
            *(float4*)(orow + 4) = make_float4(v[4], v[5], v[6], v[7]);
        } else {
            #pragma unroll
            for (int j = 0; j < 8; j++) ps[j] += v[j];
        }
    }
    if (POOL) {
        *(float4*)&red[ty*64 + tx*8]     = make_float4(ps[0], ps[1], ps[2], ps[3]);
        *(float4*)&red[ty*64 + tx*8 + 4] = make_float4(ps[4], ps[5], ps[6], ps[7]);
        __syncthreads();
        if (tid < 64) {
            float ssum = 0.f;
            #pragma unroll
            for (int g = 0; g < 32; g++) ssum += red[g*64 + tid];
            outp[b*GHD + c0 + tid] = ssum * (1.f/NN);
        }
    }
}

// ---------------- K8: final 2-layer MLP (multi-accumulator ILP) ----------------
__global__ void k_fc(const float* __restrict__ lh, const float* __restrict__ Wf1,
                     const float* __restrict__ bf1, const float* __restrict__ Wf2,
                     const float* __restrict__ bf2, float* __restrict__ out) {
    __shared__ float in_s[HH + GHD]; // 896
    __shared__ float hs[FHD];        // 256
    int b = blockIdx.x, tid = threadIdx.x; // 256 threads
    int wid = tid >> 5, lane = tid & 31;
    for (int i = tid; i < HH; i += 256) in_s[i] = lh[(size_t)b*SS*HH + i];
    if (tid < GHD) in_s[HH + tid] = g_pool[b*GHD + tid];
    __syncthreads();
    float a0 = 0.f, a1 = 0.f, a2 = 0.f, a3 = 0.f;
    #pragma unroll 8
    for (int k = 0; k < HH + GHD; k += 4) {
        a0 += in_s[k+0]*Wf1[(size_t)(k+0)*FHD + tid];
        a1 += in_s[k+1]*Wf1[(size_t)(k+1)*FHD + tid];
        a2 += in_s[k+2]*Wf1[(size_t)(k+2)*FHD + tid];
        a3 += in_s[k+3]*Wf1[(size_t)(k+3)*FHD + tid];
    }
    hs[tid] = fmaxf(bf1[tid] + (a0 + a1) + (a2 + a3), 0.f);
    __syncthreads();
    if (wid < LL) {   // warp wid computes output wid via shuffle reduce
        float o = 0.f;
        #pragma unroll
        for (int q = 0; q < FHD/32; q++)
            o += hs[q*32 + lane]*Wf2[(q*32 + lane)*LL + wid];
        #pragma unroll
        for (int off = 16; off; off >>= 1) o += __shfl_xor_sync(0xffffffffu, o, off);
        if (lane == 0) out[b*LL + wid] = o + bf2[wid];
    }
}

// ---------------- launch ----------------
extern "C" void kernel_launch(void* const* d_in, const int* in_sizes, int n_in,
                              void* d_out, int out_size) {
    const float* lh     = (const float*)d_in[0];
    const int*   submap = (const int*)d_in[1];
    const int*   ei     = (const int*)d_in[2];
    int wbase = (in_sizes[3] == 1) ? 3 : 2;  // num_nodes may be materialized
    const float* wr  = (const float*)d_in[wbase + 1];
    const float* br  = (const float*)d_in[wbase + 2];
    const float* W1  = (const float*)d_in[wbase + 3];
    const float* b1  = (const float*)d_in[wbase + 4];
    const float* W2  = (const float*)d_in[wbase + 5];
    const float* b2  = (const float*)d_in[wbase + 6];
    const float* Wf1 = (const float*)d_in[wbase + 7];
    const float* bf1 = (const float*)d_in[wbase + 8];
    const float* Wf2 = (const float*)d_in[wbase + 9];
    const float* bf2 = (const float*)d_in[wbase + 10];
    float* out = (float*)d_out;

    float *p_nf, *p_x1a, *p_x1b, *p_h1, *p_x2, *p_pool;
    cudaGetSymbolAddress((void**)&p_nf,   g_nf);
    cudaGetSymbolAddress((void**)&p_x1a,  g_x1a);
    cudaGetSymbolAddress((void**)&p_x1b,  g_x1b);
    cudaGetSymbolAddress((void**)&p_h1,   g_h1);
    cudaGetSymbolAddress((void**)&p_x2,   g_x2);
    cudaGetSymbolAddress((void**)&p_pool, g_pool);

    const int smem_seg = (NN*128 + SST*1024 + SS + NN)*sizeof(float)
                       + (SS + NN)*sizeof(int);                                     // ~103 KB
    const int smem_adj = (NN*NN + NN)*sizeof(float);                                // ~66 KB
    const int smem_ah  = (NN*NN + NN*64 + 32*64 + 64)*sizeof(float);                // ~104.5 KB
    cudaFuncSetAttribute(k_segsum,    cudaFuncAttributeMaxDynamicSharedMemorySize, smem_seg);
    cudaFuncSetAttribute(k_adj,       cudaFuncAttributeMaxDynamicSharedMemorySize, smem_adj);
    cudaFuncSetAttribute(k_ah<false>, cudaFuncAttributeMaxDynamicSharedMemorySize, smem_ah);
    cudaFuncSetAttribute(k_ah<true>,  cudaFuncAttributeMaxDynamicSharedMemorySize, smem_ah);

    k_gate<<<(BB*SS*32)/256, 256>>>(lh, wr, br);
    k_segsum<<<dim3(6, BB), 128, smem_seg>>>(lh, submap);
    k_adj<<<BB, 256, smem_adj>>>(ei);
    // GEMM1: K=768 split into two 384-halves (y-dim), disjoint outputs
    k_mma<<<dim3(BNN/64, 2), 256>>>(p_nf, W1, p_x1a, p_x1b, HH, HH/2);
    k_ah<false><<<BB*2, 256, smem_ah>>>(p_x1a, p_x1b, b1, p_h1);
    // GEMM2: K=128, no split
    k_mma<<<dim3(BNN/64, 1), 256>>>(p_h1, W2, p_x2, p_x2, GHD, GHD);
    k_ah<true><<<BB*2, 256, smem_ah>>>(p_x2, (const float*)0, b2, p_pool);
    k_fc<<<BB, 256>>>(lh, Wf1, bf1, Wf2, bf2, out);
}

// round 16
// speedup vs baseline: 1.3996x; 1.1133x over previous
#include <cuda_runtime.h>
#include <math.h>
#include <stdint.h>

// Problem constants
#define BB  64
#define SS  512
#define HH  768
#define NN  128
#define EE  1024
#define GHD 128
#define FHD 256
#define LL  2
#define BNN (BB*NN)   // 8192
#define SST 8         // segsum ring slots
#define SIF 6         // segsum in-flight groups
#define APITCH 20     // As row pitch (floats) - conflict-free
#define BPITCH 136    // Bs row pitch (floats) - conflict-free

// ---------------- scratch (device globals; no allocation allowed) ----------------
__device__ float g_gate[BB*SS];
__device__ float g_nf[(size_t)BNN*HH];        // 25 MB
__device__ float g_adj[(size_t)BB*NN*NN];     // 4 MB, [b][d][s]  (row-major d x s)
__device__ float g_x1a[(size_t)BNN*GHD];
__device__ float g_x1b[(size_t)BNN*GHD];
__device__ float g_h1[(size_t)BNN*GHD];
__device__ float g_x2[(size_t)BNN*GHD];
__device__ float g_pool[BB*GHD];

// ---------------- helpers ----------------
__device__ __forceinline__ void cp16(void* smem, const void* g) {
    unsigned a = (unsigned)__cvta_generic_to_shared(smem);
    asm volatile("cp.async.cg.shared.global [%0], [%1], 16;\n" :: "r"(a), "l"(g));
}
__device__ __forceinline__ void mma_tf32(float* c, const uint32_t* a,
                                         uint32_t b0, uint32_t b1) {
    asm volatile(
        "mma.sync.aligned.m16n8k8.row.col.f32.tf32.tf32.f32 "
        "{%0,%1,%2,%3}, {%4,%5,%6,%7}, {%8,%9}, {%0,%1,%2,%3};"
        : "+f"(c[0]), "+f"(c[1]), "+f"(c[2]), "+f"(c[3])
        : "r"(a[0]), "r"(a[1]), "r"(a[2]), "r"(a[3]), "r"(b0), "r"(b1));
}

// ---------------- K0: zero pooled accumulator (graph-replay safe) ----------------
__global__ void k_zero() {
    int i = blockIdx.x*256 + threadIdx.x;
    if (i < BB*GHD) g_pool[i] = 0.f;
}

// ---------------- K1: gate = sigmoid(lh . wr + br) ----------------
__global__ void k_gate(const float* __restrict__ lh,
                       const float* __restrict__ wr, const float* __restrict__ brp) {
    int warp = (blockIdx.x*blockDim.x + threadIdx.x) >> 5;
    int lane = threadIdx.x & 31;
    if (warp >= BB*SS) return;
    const float4* row4 = (const float4*)(lh + (size_t)warp*HH);
    const float4* w4   = (const float4*)wr;
    float dot = 0.f;
    #pragma unroll
    for (int i = 0; i < 6; i++) {
        float4 a = row4[lane + 32*i];
        float4 w = w4[lane + 32*i];
        dot += a.x*w.x + a.y*w.y + a.z*w.z + a.w*w.w;
    }
    #pragma unroll
    for (int off = 16; off; off >>= 1) dot += __shfl_xor_sync(0xffffffffu, dot, off);
    if (lane == 0)
        g_gate[warp] = 1.f/(1.f + expf(-(dot + brp[0])));
}

// ---------------- K2: segment mean — 8-slot cp.async ring, thread-private cols ----
__global__ void k_segsum(const float* __restrict__ lh, const int* __restrict__ submap) {
    extern __shared__ float sm[];
    float* acc    = sm;                       // NN*128 (64 KB)
    float* stage  = sm + NN*128;              // SST*8*128 (32 KB)
    float* gate_s = stage + SST*1024;         // SS
    float* rc     = gate_s + SS;              // NN
    int*   sub_s  = (int*)(rc + NN);          // SS
    int*   cnt_s  = sub_s + SS;               // NN
    int b = blockIdx.y, c0 = blockIdx.x*128, tid = threadIdx.x;

    const float* base = lh + (size_t)b*SS*HH + c0;
    int r  = tid >> 5;          // 0..3
    int c4 = (tid & 31)*4;
    #pragma unroll
    for (int g = 0; g < SIF; g++) {
        const float* p = base + (size_t)(g*8)*HH;
        cp16(&stage[(g & (SST-1))*1024 + r*128 + c4],     p + (size_t)r*HH + c4);
        cp16(&stage[(g & (SST-1))*1024 + (r+4)*128 + c4], p + (size_t)(r+4)*HH + c4);
        asm volatile("cp.async.commit_group;\n" ::: "memory");
    }

    float4* a4 = (float4*)acc;
    for (int i = tid; i < NN*32; i += 128) a4[i] = make_float4(0.f,0.f,0.f,0.f);
    if (tid < NN) cnt_s[tid] = 0;
    for (int s = tid; s < SS; s += 128) {
        gate_s[s] = g_gate[b*SS + s];
        sub_s[s]  = submap[b*SS + s];
    }
    __syncthreads();
    for (int s = tid; s < SS; s += 128) atomicAdd(&cnt_s[sub_s[s]], 1);

    for (int g = 0; g < SS/8; g++) {
        int st = g & (SST-1);
        asm volatile("cp.async.wait_group %0;\n" :: "n"(SIF-1) : "memory");
        __syncthreads();
        float v[8];
        #pragma unroll
        for (int j = 0; j < 8; j++) v[j] = stage[st*1024 + j*128 + tid];
        int gn = g + SIF;
        if (gn < SS/8) {
            int wn = gn & (SST-1);
            const float* p = base + (size_t)(gn*8)*HH;
            cp16(&stage[wn*1024 + r*128 + c4],     p + (size_t)r*HH + c4);
            cp16(&stage[wn*1024 + (r+4)*128 + c4], p + (size_t)(r+4)*HH + c4);
        }
        asm volatile("cp.async.commit_group;\n" ::: "memory");
        int s0 = g*8;
        #pragma unroll
        for (int j = 0; j < 8; j++) {
            int n = sub_s[s0+j];
            acc[n*128 + tid] += v[j]*gate_s[s0+j];   // private column: no atomic
        }
    }
    __syncthreads();
    if (tid < NN) rc[tid] = 1.f/fmaxf((float)cnt_s[tid], 1.f);
    __syncthreads();
    for (int n = 0; n < NN; n++)
        g_nf[((size_t)(b*NN + n))*HH + c0 + tid] = acc[n*128 + tid]*rc[n];
}

// ---------------- K3: dense normalized adjacency, [d][s] row-major ----------------
__global__ void k_adj(const int* __restrict__ ei) {
    extern __shared__ float sm[];
    float* cnt = sm;          // NN*NN, [d][s]
    float* deg = sm + NN*NN;  // NN
    int b = blockIdx.x, tid = threadIdx.x;   // 256 threads
    float4* c4 = (float4*)cnt;
    for (int i = tid; i < NN*NN/4; i += 256) c4[i] = make_float4(0.f,0.f,0.f,0.f);
    if (tid < NN) deg[tid] = 1.f;   // self loop
    __syncthreads();
    const int* sP = ei + (size_t)b*2*EE;
    const int* dP = sP + EE;
    for (int e = tid; e < EE; e += 256) {
        int s = sP[e], d = dP[e];
        atomicAdd(&deg[d], 1.f);
        atomicAdd(&cnt[d*NN + s], 1.f);
    }
    __syncthreads();
    if (tid < NN) deg[tid] = rsqrtf(deg[tid]);
    __syncthreads();
    float* outp = g_adj + (size_t)b*NN*NN;
    for (int i = tid; i < NN*NN; i += 256) {
        int d = i >> 7, s = i & 127;
        float v = cnt[i] + (s == d ? 1.f : 0.f);
        outp[i] = v * deg[d] * deg[s];
    }
}

// ---------------- K4/K6: tf32 mma.sync GEMM, 8 warps, K-split ---------------------
// C[BNN x 128] = A[:, k0:k0+KC] @ W[k0:k0+KC, :]; raw fp32, HW tf32 truncation.
__global__ void __launch_bounds__(256) k_mma(const float* __restrict__ A,
                                             const float* __restrict__ B,
                                             float* __restrict__ Ca,
                                             float* __restrict__ Cb,
                                             int K, int KC) {
    __shared__ float As[2][64][APITCH];
    __shared__ float Bs[2][16][BPITCH];
    int tid = threadIdx.x, lane = tid & 31, wid = tid >> 5;
    int wm = wid & 3, wn = wid >> 2;
    int row0 = blockIdx.x*64;
    int k0 = blockIdx.y * KC;
    float* C = blockIdx.y ? Cb : Ca;
    int r = lane >> 2, c = lane & 3;

    auto loadStage = [&](int st, int kk) {
        {
            int row = tid >> 2, k4 = (tid & 3)*4;
            cp16(&As[st][row][k4], A + (size_t)(row0 + row)*K + k0 + kk + k4);
        }
        #pragma unroll
        for (int q = 0; q < 2; q++) {
            int idx = tid*2 + q;
            int row = idx >> 5, cc = (idx & 31)*4;
            cp16(&Bs[st][row][cc], B + (size_t)(k0 + kk + row)*GHD + cc);
        }
        asm volatile("cp.async.commit_group;\n" ::: "memory");
    };
    loadStage(0, 0);

    float acc[8][4];
    #pragma unroll
    for (int j = 0; j < 8; j++)
        #pragma unroll
        for (int q = 0; q < 4; q++) acc[j][q] = 0.f;

    int nk = KC >> 4;
    for (int kb = 0; kb < nk; kb++) {
        int st = kb & 1;
        if (kb + 1 < nk) {
            loadStage(st^1, (kb + 1) << 4);
            asm volatile("cp.async.wait_group 1;\n" ::: "memory");
        } else {
            asm volatile("cp.async.wait_group 0;\n" ::: "memory");
        }
        __syncthreads();
        #pragma unroll
        for (int ks = 0; ks < 16; ks += 8) {
            uint32_t a[4];
            int rr = wm*16 + r;
            a[0] = __float_as_uint(As[st][rr    ][ks + c]);
            a[1] = __float_as_uint(As[st][rr + 8][ks + c]);
            a[2] = __float_as_uint(As[st][rr    ][ks + c + 4]);
            a[3] = __float_as_uint(As[st][rr + 8][ks + c + 4]);
            #pragma unroll
            for (int j = 0; j < 8; j++) {
                int nc = wn*64 + j*8 + r;
                uint32_t b0 = __float_as_uint(Bs[st][ks + c    ][nc]);
                uint32_t b1 = __float_as_uint(Bs[st][ks + c + 4][nc]);
                mma_tf32(acc[j], a, b0, b1);
            }
        }
        __syncthreads();
    }
    {
        int rr = row0 + wm*16 + r;
        #pragma unroll
        for (int j = 0; j < 8; j++) {
            int cc = wn*64 + j*8 + 2*c;
            *(float2*)&C[(size_t)rr*GHD + cc]       = make_float2(acc[j][0], acc[j][1]);
            *(float2*)&C[(size_t)(rr + 8)*GHD + cc] = make_float2(acc[j][2], acc[j][3]);
        }
    }
}

// ---------------- K5/K7: GCN aggregation via tf32 mma ----------------------------
// out[d][c] = relu( sum_s Adj[b][d][s] * (Xa+Xb)[b][s][c] + bias[c] )
// grid = BB*2 (64-row d-tiles); POOL accumulates column sums into pre-zeroed outp.
template <int AD, int POOL>
__global__ void __launch_bounds__(256) k_ahm(const float* __restrict__ Xa,
                                             const float* __restrict__ Xb,
                                             const float* __restrict__ bias,
                                             float* __restrict__ outp) {
    __shared__ float As[2][64][APITCH];
    __shared__ float Bs[2][16][BPITCH];
    __shared__ float bias_s[GHD];
    __shared__ float red[8][68];
    int tid = threadIdx.x, lane = tid & 31, wid = tid >> 5;
    int wm = wid & 3, wn = wid >> 2;
    int bx = blockIdx.x;
    int b = bx >> 1, row0 = (bx & 1)*64;
    int r = lane >> 2, c = lane & 3;
    const float* A   = g_adj + (size_t)b*NN*NN;           // [d][s], ld = NN
    const float* XaB = Xa + (size_t)b*NN*GHD;
    const float* XbB = AD ? Xb + (size_t)b*NN*GHD : (const float*)0;

    int brow = tid >> 4;            // 0..15 (B k-row within chunk)
    int bcb  = (tid & 15)*8;        // 8-float column span

    auto loadA = [&](int st, int kk) {
        int row = tid >> 2, k4 = (tid & 3)*4;
        cp16(&As[st][row][k4], A + (size_t)(row0 + row)*NN + kk + k4);
        asm volatile("cp.async.commit_group;\n" ::: "memory");
    };
    auto loadB = [&](int kk, float4* bReg) {
        const float* p = XaB + (size_t)(kk + brow)*GHD + bcb;
        bReg[0] = *(const float4*)p;
        bReg[1] = *(const float4*)(p + 4);
        if (AD) {
            const float* q = XbB + (size_t)(kk + brow)*GHD + bcb;
            float4 w0 = *(const float4*)q;
            float4 w1 = *(const float4*)(q + 4);
            bReg[0].x += w0.x; bReg[0].y += w0.y; bReg[0].z += w0.z; bReg[0].w += w0.w;
            bReg[1].x += w1.x; bReg[1].y += w1.y; bReg[1].z += w1.z; bReg[1].w += w1.w;
        }
    };

    loadA(0, 0);
    float4 bReg[2];
    loadB(0, bReg);
    if (tid < GHD) bias_s[tid] = bias[tid];

    float acc[8][4];
    #pragma unroll
    for (int j = 0; j < 8; j++)
        #pragma unroll
        for (int q = 0; q < 4; q++) acc[j][q] = 0.f;

    const int nk = NN/16;   // 8
    for (int kb = 0; kb < nk; kb++) {
        int st = kb & 1;
        if (kb + 1 < nk) {
            loadA(st^1, (kb + 1) << 4);
            asm volatile("cp.async.wait_group 1;\n" ::: "memory");
        } else {
            asm volatile("cp.async.wait_group 0;\n" ::: "memory");
        }
        // stage current B chunk into smem
        *(float4*)&Bs[st][brow][bcb]     = bReg[0];
        *(float4*)&Bs[st][brow][bcb + 4] = bReg[1];
        float4 bNext[2];
        bNext[0] = make_float4(0.f,0.f,0.f,0.f);
        bNext[1] = make_float4(0.f,0.f,0.f,0.f);
        if (kb + 1 < nk) loadB((kb + 1) << 4, bNext);
        __syncthreads();
        #pragma unroll
        for (int ks = 0; ks < 16; ks += 8) {
            uint32_t a[4];
            int rr = wm*16 + r;
            a[0] = __float_as_uint(As[st][rr    ][ks + c]);
            a[1] = __float_as_uint(As[st][rr + 8][ks + c]);
            a[2] = __float_as_uint(As[st][rr    ][ks + c + 4]);
            a[3] = __float_as_uint(As[st][rr + 8][ks + c + 4]);
            #pragma unroll
            for (int j = 0; j < 8; j++) {
                int nc = wn*64 + j*8 + r;
                uint32_t b0 = __float_as_uint(Bs[st][ks + c    ][nc]);
                uint32_t b1 = __float_as_uint(Bs[st][ks + c + 4][nc]);
                mma_tf32(acc[j], a, b0, b1);
            }
        }
        bReg[0] = bNext[0]; bReg[1] = bNext[1];
        __syncthreads();
    }

    if (!POOL) {
        int rr0 = row0 + wm*16 + r;
        #pragma unroll
        for (int j = 0; j < 8; j++) {
            int cc = wn*64 + j*8 + 2*c;
            float v0 = fmaxf(acc[j][0] + bias_s[cc],   0.f);
            float v1 = fmaxf(acc[j][1] + bias_s[cc+1], 0.f);
            float v2 = fmaxf(acc[j][2] + bias_s[cc],   0.f);
            float v3 = fmaxf(acc[j][3] + bias_s[cc+1], 0.f);
            *(float2*)&outp[(size_t)(b*NN + rr0)*GHD + cc]     = make_float2(v0, v1);
            *(float2*)&outp[(size_t)(b*NN + rr0 + 8)*GHD + cc] = make_float2(v2, v3);
        }
    } else {
        float ps[16];
        #pragma unroll
        for (int j = 0; j < 8; j++) {
            int cc = wn*64 + j*8 + 2*c;
            float v0 = fmaxf(acc[j][0] + bias_s[cc],   0.f);
            float v1 = fmaxf(acc[j][1] + bias_s[cc+1], 0.f);
            float v2 = fmaxf(acc[j][2] + bias_s[cc],   0.f);
            float v3 = fmaxf(acc[j][3] + bias_s[cc+1], 0.f);
            ps[2*j]   = v0 + v2;
            ps[2*j+1] = v1 + v3;
        }
        // reduce over r (lanes differing in bits 2..4)
        #pragma unroll
        for (int off = 4; off <= 16; off <<= 1)
            #pragma unroll
            for (int t = 0; t < 16; t++)
                ps[t] += __shfl_xor_sync(0xffffffffu, ps[t], off);
        if (r == 0) {   // lanes 0..3 (= c)
            #pragma unroll
            for (int j = 0; j < 8; j++) {
                red[wid][j*8 + 2*c]     = ps[2*j];
                red[wid][j*8 + 2*c + 1] = ps[2*j+1];
            }
        }
        __syncthreads();
        if (tid < GHD) {
            int half = tid >> 6, lc = tid & 63;
            float s = red[half*4 + 0][lc] + red[half*4 + 1][lc]
                    + red[half*4 + 2][lc] + red[half*4 + 3][lc];
            atomicAdd(&outp[b*GHD + tid], s * (1.f/NN));
        }
    }
}

// ---------------- K8: final 2-layer MLP (multi-accumulator ILP) ----------------
__global__ void k_fc(const float* __restrict__ lh, const float* __restrict__ Wf1,
                     const float* __restrict__ bf1, const float* __restrict__ Wf2,
                     const float* __restrict__ bf2, float* __restrict__ out) {
    __shared__ float in_s[HH + GHD]; // 896
    __shared__ float hs[FHD];        // 256
    int b = blockIdx.x, tid = threadIdx.x; // 256 threads
    int wid = tid >> 5, lane = tid & 31;
    for (int i = tid; i < HH; i += 256) in_s[i] = lh[(size_t)b*SS*HH + i];
    if (tid < GHD) in_s[HH + tid] = g_pool[b*GHD + tid];
    __syncthreads();
    float a0 = 0.f, a1 = 0.f, a2 = 0.f, a3 = 0.f;
    #pragma unroll 8
    for (int k = 0; k < HH + GHD; k += 4) {
        a0 += in_s[k+0]*Wf1[(size_t)(k+0)*FHD + tid];
        a1 += in_s[k+1]*Wf1[(size_t)(k+1)*FHD + tid];
        a2 += in_s[k+2]*Wf1[(size_t)(k+2)*FHD + tid];
        a3 += in_s[k+3]*Wf1[(size_t)(k+3)*FHD + tid];
    }
    hs[tid] = fmaxf(bf1[tid] + (a0 + a1) + (a2 + a3), 0.f);
    __syncthreads();
    if (wid < LL) {
        float o = 0.f;
        #pragma unroll
        for (int q = 0; q < FHD/32; q++)
            o += hs[q*32 + lane]*Wf2[(q*32 + lane)*LL + wid];
        #pragma unroll
        for (int off = 16; off; off >>= 1) o += __shfl_xor_sync(0xffffffffu, o, off);
        if (lane == 0) out[b*LL + wid] = o + bf2[wid];
    }
}

// ---------------- launch ----------------
extern "C" void kernel_launch(void* const* d_in, const int* in_sizes, int n_in,
                              void* d_out, int out_size) {
    const float* lh     = (const float*)d_in[0];
    const int*   submap = (const int*)d_in[1];
    const int*   ei     = (const int*)d_in[2];
    int wbase = (in_sizes[3] == 1) ? 3 : 2;  // num_nodes may be materialized
    const float* wr  = (const float*)d_in[wbase + 1];
    const float* br  = (const float*)d_in[wbase + 2];
    const float* W1  = (const float*)d_in[wbase + 3];
    const float* b1  = (const float*)d_in[wbase + 4];
    const float* W2  = (const float*)d_in[wbase + 5];
    const float* b2  = (const float*)d_in[wbase + 6];
    const float* Wf1 = (const float*)d_in[wbase + 7];
    const float* bf1 = (const float*)d_in[wbase + 8];
    const float* Wf2 = (const float*)d_in[wbase + 9];
    const float* bf2 = (const float*)d_in[wbase + 10];
    float* out = (float*)d_out;

    float *p_nf, *p_x1a, *p_x1b, *p_h1, *p_x2, *p_pool;
    cudaGetSymbolAddress((void**)&p_nf,   g_nf);
    cudaGetSymbolAddress((void**)&p_x1a,  g_x1a);
    cudaGetSymbolAddress((void**)&p_x1b,  g_x1b);
    cudaGetSymbolAddress((void**)&p_h1,   g_h1);
    cudaGetSymbolAddress((void**)&p_x2,   g_x2);
    cudaGetSymbolAddress((void**)&p_pool, g_pool);

    const int smem_seg = (NN*128 + SST*1024 + SS + NN)*sizeof(float)
                       + (SS + NN)*sizeof(int);                                     // ~103 KB
    const int smem_adj = (NN*NN + NN)*sizeof(float);                                // ~66 KB
    cudaFuncSetAttribute(k_segsum, cudaFuncAttributeMaxDynamicSharedMemorySize, smem_seg);
    cudaFuncSetAttribute(k_adj,    cudaFuncAttributeMaxDynamicSharedMemorySize, smem_adj);

    k_zero<<<(BB*GHD + 255)/256, 256>>>();
    k_gate<<<(BB*SS*32)/256, 256>>>(lh, wr, br);
    k_segsum<<<dim3(6, BB), 128, smem_seg>>>(lh, submap);
    k_adj<<<BB, 256, smem_adj>>>(ei);
    // GEMM1: K=768 split into two 384-halves (y-dim), disjoint outputs
    k_mma<<<dim3(BNN/64, 2), 256>>>(p_nf, W1, p_x1a, p_x1b, HH, HH/2);
    // Aggregation 1: adds x1a+x1b in the B loader, relu+bias epilogue
    k_ahm<1,0><<<BB*2, 256>>>(p_x1a, p_x1b, b1, p_h1);
    // GEMM2: K=128, no split
    k_mma<<<dim3(BNN/64, 1), 256>>>(p_h1, W2, p_x2, p_x2, GHD, GHD);
    // Aggregation 2: pooled column sums into pre-zeroed g_pool
    k_ahm<0,1><<<BB*2, 256>>>(p_x2, p_x2, b2, p_pool);
    k_fc<<<BB, 256>>>(lh, Wf1, bf1, Wf2, bf2, out);
}